// round 8
// baseline (speedup 1.0000x reference)
#include <cuda_runtime.h>

// Shapes (fixed)
#define B_ 32
#define P_ 196
#define D_ 512
#define H_ 8
#define U_ 4
#define C_ 500

#define KNOWN_ELEMS (B_ * C_ * (H_ + 3) * D_)   // 90,112,000
#define UNK_ELEMS   (B_ * (U_ + 3) * D_)        // 114,688

#define NUNITS   (B_ * C_)      // 16000 known prompt units
#define CAP1     10000          // static-units drained in window 1

// smem plan (floats), union across phases:
//  A: q_sh 4096 | B: w_sh 1568 + stats + psum(1024) = 2624 | C: Tsh 2048 + Wsh 2080 = 4128
#define SMEM_FLOATS 4160
#define SMEM_BYTES  (SMEM_FLOATS * 4)

// Scratch
__device__ float g_dom[B_ * D_];
__device__ float g_sem[B_ * H_ * D_];
__device__ float g_scores[B_ * P_ * H_];
__device__ unsigned g_bar_count;
__device__ volatile unsigned g_bar_gen;
__device__ unsigned g_t1, g_t2;     // static-write ticket counters

__device__ __forceinline__ void grid_barrier() {
    __syncthreads();
    if (threadIdx.x == 0) {
        __threadfence();
        unsigned gen = g_bar_gen;
        if (atomicAdd(&g_bar_count, 1u) == gridDim.x - 1) {
            g_bar_count = 0;
            __threadfence();
            g_bar_gen = gen + 1;
        } else {
            while (g_bar_gen == gen) __nanosleep(64);
        }
        __threadfence();
    }
    __syncthreads();
}

// Write the data-independent tokens (prefix + suffix) of known unit u.
__device__ __forceinline__ void write_static_unit(int u, const float4* pre,
                                                  const float4* suf, float4* out) {
    const int c = u % C_;
    float4* o = out + (size_t)u * (11 * 128);
    const float4* prow = pre + (size_t)c * 128;
    const float4* srow = suf + (size_t)c * 128;
    const int tid = threadIdx.x;
    // 256 threads: half write prefix token 0, half write suffix token 10
    const int half = tid >> 7, j = tid & 127;
    const float4 v = half ? srow[j] : prow[j];
    __stcs(&o[half * (10 * 128) + j], v);
}

__global__ __launch_bounds__(256, 6)
void k_all(const float* __restrict__ patch,
           const float* __restrict__ gf,
           const float* __restrict__ query,
           const float* __restrict__ domW,
           const float* __restrict__ domb,
           const float* __restrict__ semW,
           const float* __restrict__ semb,
           const float4* __restrict__ usem,
           const float4* __restrict__ pre,
           const float4* __restrict__ suf,
           const float4* __restrict__ upre,
           const float4* __restrict__ usuf,
           float4* __restrict__ out,
           float4* __restrict__ unk_out,
           float* __restrict__ sem_out)
{
    extern __shared__ float sh[];
    __shared__ int tkt_sh;
    const int tid  = threadIdx.x;
    const int warp = tid >> 5, lane = tid & 31;
    const unsigned NB = gridDim.x;

    // ===================== Phase A: scores ================================
    if (blockIdx.x == 0 && tid == 0) { g_t1 = 0; g_t2 = 0; }
    {
        float4* q_sh = (float4*)sh;         // 8 heads x 128 float4 = 16 KB
        for (int i = tid; i < H_ * 128; i += 256)
            q_sh[i] = ((const float4*)query)[i];
        __syncthreads();

        for (int gw = blockIdx.x * 8 + warp; gw < B_ * P_; gw += NB * 8) {
            const int b = gw / P_;
            const int p = gw - b * P_;
            const float4* row = (const float4*)(patch + ((size_t)b * P_ + p) * D_);
            float acc[H_];
#pragma unroll
            for (int h = 0; h < H_; h++) acc[h] = 0.f;
#pragma unroll
            for (int i = 0; i < 4; i++) {
                float4 x = row[lane + i * 32];
#pragma unroll
                for (int h = 0; h < H_; h++) {
                    float4 q = q_sh[h * 128 + lane + i * 32];
                    acc[h] += x.x * q.x + x.y * q.y + x.z * q.z + x.w * q.w;
                }
            }
#pragma unroll
            for (int h = 0; h < H_; h++) {
#pragma unroll
                for (int o = 16; o; o >>= 1)
                    acc[h] += __shfl_xor_sync(0xffffffffu, acc[h], o);
            }
            if (lane == 0) {
                float* s = g_scores + ((size_t)b * P_ + p) * H_;
#pragma unroll
                for (int h = 0; h < H_; h++) s[h] = acc[h];
            }
        }
    }
    grid_barrier();

    // ============ Window 1: pool (blocks 0..127) || static writes =========
    if (blockIdx.x < B_ * 4) {
        const int t  = blockIdx.x;
        const int b  = t >> 2;
        const int dt = t & 3;

        float* w_sh  = sh;            // 1568
        float* mmax  = sh + 1568;     // 8
        float* inv_s = sh + 1576;     // 8
        float* psum  = sh + 1600;     // 1024

        const float* sc = g_scores + (size_t)b * P_ * H_;
        for (int i = tid; i < P_ * H_; i += 256) w_sh[i] = sc[i];
        __syncthreads();
        {
            const int h = warp;       // 8 warps = 8 heads
            float m = -1e30f;
            for (int p = lane; p < P_; p += 32) m = fmaxf(m, w_sh[p * H_ + h]);
#pragma unroll
            for (int o = 16; o; o >>= 1) m = fmaxf(m, __shfl_xor_sync(0xffffffffu, m, o));
            float s = 0.f;
            for (int p = lane; p < P_; p += 32) s += __expf(w_sh[p * H_ + h] - m);
#pragma unroll
            for (int o = 16; o; o >>= 1) s += __shfl_xor_sync(0xffffffffu, s, o);
            if (lane == 0) { mmax[h] = m; inv_s[h] = 1.f / s; }
        }
        __syncthreads();
        for (int i = tid; i < P_ * H_; i += 256) {
            int h = i & (H_ - 1);
            w_sh[i] = __expf(w_sh[i] - mmax[h]) * inv_s[h];
        }
        __syncthreads();

        const int d_local = tid & 127;
        const int phalf   = tid >> 7;
        const int d       = dt * 128 + d_local;
        const int p0      = phalf * 98;
        const float* pb = patch + (size_t)b * P_ * D_ + d;

        float acc[H_];
#pragma unroll
        for (int h = 0; h < H_; h++) acc[h] = 0.f;
        for (int p = p0; p < p0 + 98; p += 2) {
            float x0 = pb[(p + 0) * D_];
            float x1 = pb[(p + 1) * D_];
#pragma unroll
            for (int h = 0; h < H_; h++) {
                acc[h] = fmaf(w_sh[(p + 0) * H_ + h], x0, acc[h]);
                acc[h] = fmaf(w_sh[(p + 1) * H_ + h], x1, acc[h]);
            }
        }
        if (phalf == 1) {
#pragma unroll
            for (int h = 0; h < H_; h++) psum[d_local * H_ + h] = acc[h];
        }
        __syncthreads();
        if (phalf == 0) {
#pragma unroll
            for (int h = 0; h < H_; h++)
                sem_out[((size_t)b * H_ + h) * D_ + d] = acc[h] + psum[d_local * H_ + h];
        }
    }
    // drain static tickets [0, CAP1)
    while (true) {
        if (tid == 0) tkt_sh = (int)atomicAdd(&g_t1, 1u);
        __syncthreads();
        const int t = tkt_sh;
        __syncthreads();
        if (t >= CAP1) break;
        write_static_unit(t, pre, suf, out);
    }
    grid_barrier();

    // ============ Window 2: proj (blocks 0..143) || static writes =========
    if (blockIdx.x < 9 * 16) {
        const int y  = blockIdx.x >> 4;        // 0..8 (8 = domain)
        const int e0 = (blockIdx.x & 15) * 32;
        const bool dom = (y == 8);

        float*  Tsh  = sh;                     // 32 x 64 floats (float4 rows)
        float4* Tsh4 = (float4*)sh;
        float*  Wsh  = sh + 2048;              // 32 x 65 floats (padded)

        const float* Tbase   = dom ? gf : (sem_out + (size_t)y * D_);
        const size_t Tstride = dom ? (size_t)D_ : (size_t)H_ * D_;
        const float* Wbase   = dom ? (domW + (size_t)e0 * D_)
                                   : (semW + ((size_t)y * D_ + e0) * D_);

        const int e_local = tid & 31;
        const int bq      = tid >> 5;          // 0..7
        float acc[4] = {0.f, 0.f, 0.f, 0.f};

        for (int kc = 0; kc < D_; kc += 64) {
            // fill T (32 b-rows x 64 k) and W (32 e-rows x 64 k, padded 65)
            {
                const int bi = tid >> 4, kq = tid & 15;    // 512 slots, 256 thr x2
#pragma unroll
                for (int rep = 0; rep < 2; rep++) {
                    const int r = bi + rep * 16;
                    Tsh4[r * 16 + kq] =
                        ((const float4*)(Tbase + r * Tstride + kc))[kq];
                    float4 w = ((const float4*)(Wbase + (size_t)r * D_ + kc))[kq];
                    float* wd = Wsh + r * 65 + kq * 4;
                    wd[0] = w.x; wd[1] = w.y; wd[2] = w.z; wd[3] = w.w;
                }
            }
            __syncthreads();
#pragma unroll 4
            for (int k4 = 0; k4 < 16; k4++) {
                const float* wk = Wsh + e_local * 65 + k4 * 4;
                const float w0 = wk[0], w1 = wk[1], w2 = wk[2], w3 = wk[3];
#pragma unroll
                for (int j = 0; j < 4; j++) {
                    float4 tv = Tsh4[(bq + 8 * j) * 16 + k4];
                    acc[j] = fmaf(tv.x, w0, acc[j]);
                    acc[j] = fmaf(tv.y, w1, acc[j]);
                    acc[j] = fmaf(tv.z, w2, acc[j]);
                    acc[j] = fmaf(tv.w, w3, acc[j]);
                }
            }
            __syncthreads();
        }
        const int e = e0 + e_local;
#pragma unroll
        for (int j = 0; j < 4; j++) {
            const int b = bq + 8 * j;
            if (dom) g_dom[b * D_ + e] = acc[j] + domb[e];
            else     g_sem[((size_t)b * H_ + y) * D_ + e] = acc[j] + semb[y * D_ + e];
        }
    }
    // drain static tickets [CAP1, NUNITS)
    while (true) {
        if (tid == 0) tkt_sh = CAP1 + (int)atomicAdd(&g_t2, 1u);
        __syncthreads();
        const int t = tkt_sh;
        __syncthreads();
        if (t >= NUNITS) break;
        write_static_unit(t, pre, suf, out);
    }
    grid_barrier();

    // ============ Phase D: dependent tokens (288 MB) + unknown ============
    for (int u = blockIdx.x; u < NUNITS + B_; u += NB) {
        if (u < NUNITS) {
            const int b = u / C_;
            float4* o = out + (size_t)u * (11 * 128) + 128;   // tokens 1..9
            const float4* dm = ((const float4*)g_dom) + b * 128;
            const float4* sm = ((const float4*)g_sem) + (size_t)b * H_ * 128;
            for (int i = tid; i < 9 * 128; i += 256) {
                const int tk = i >> 7, j = i & 127;
                const float4 v = (tk == 0) ? dm[j] : sm[(tk - 1) * 128 + j];
                __stcs(&o[i], v);
            }
        } else {
            const int b = u - NUNITS;
            float4* o = unk_out + (size_t)b * 7 * 128;
            const float4* dm = ((const float4*)g_dom) + b * 128;
            for (int i = tid; i < 7 * 128; i += 256) {
                const int tk = i >> 7, j = i & 127;
                float4 v;
                if (tk == 0)      v = upre[j];
                else if (tk == 1) v = dm[j];
                else if (tk < 6)  v = usem[(tk - 2) * 128 + j];
                else              v = usuf[j];
                __stcs(&o[i], v);
            }
        }
    }
}

// ---------------------------------------------------------------------------
extern "C" void kernel_launch(void* const* d_in, const int* in_sizes, int n_in,
                              void* d_out, int out_size) {
    const float* patch = (const float*)d_in[0];
    const float* gf    = (const float*)d_in[1];
    const float* query = (const float*)d_in[2];
    const float* domW  = (const float*)d_in[3];
    const float* domb  = (const float*)d_in[4];
    const float* semW  = (const float*)d_in[5];
    const float* semb  = (const float*)d_in[6];
    const float* usem  = (const float*)d_in[7];
    const float* pre   = (const float*)d_in[8];
    const float* suf   = (const float*)d_in[9];
    const float* upre  = (const float*)d_in[10];
    const float* usuf  = (const float*)d_in[11];

    float* out     = (float*)d_out;
    float* unk_out = out + (size_t)KNOWN_ELEMS;
    float* sem_out = out + (size_t)KNOWN_ELEMS + UNK_ELEMS;

    cudaFuncSetAttribute(k_all, cudaFuncAttributeMaxDynamicSharedMemorySize,
                         SMEM_BYTES);

    // Size the persistent grid to exactly the co-resident capacity.
    // Host-side API calls happen at capture time, not replay — capture-safe.
    int dev = 0, nsm = 148, per_sm = 6;
    cudaGetDevice(&dev);
    cudaDeviceGetAttribute(&nsm, cudaDevAttrMultiProcessorCount, dev);
    cudaOccupancyMaxActiveBlocksPerMultiprocessor(&per_sm, k_all, 256, SMEM_BYTES);
    if (per_sm < 1) per_sm = 1;
    int nblk = nsm * per_sm;
    if (nblk < 160) nblk = 160;   // must cover pool(128)/proj(144) one-shot maps

    k_all<<<nblk, 256, SMEM_BYTES>>>(
        patch, gf, query, domW, domb, semW, semb,
        (const float4*)usem, (const float4*)pre, (const float4*)suf,
        (const float4*)upre, (const float4*)usuf,
        (float4*)out, (float4*)unk_out, sem_out);
}

// round 9
// speedup vs baseline: 1.5727x; 1.5727x over previous
#include <cuda_runtime.h>

// Shapes (fixed)
#define B_ 32
#define P_ 196
#define D_ 512
#define H_ 8
#define U_ 4
#define C_ 500

#define KNOWN_ELEMS (B_ * C_ * (H_ + 3) * D_)   // 90,112,000
#define UNK_ELEMS   (B_ * (U_ + 3) * D_)        // 114,688
#define NUNITS      (B_ * C_)                    // 16000

// Scratch (device globals — no allocation allowed)
__device__ float g_dom[B_ * D_];
__device__ float g_sem[B_ * H_ * D_];
__device__ float g_scores[B_ * P_ * H_];

// ---------------------------------------------------------------------------
// Kernel 1: scores[b,p,h] = patch[b,p,:] . query[h,:]
// grid 784 x 256 thr, warp per (b,p), float4 MLP=4.
// ---------------------------------------------------------------------------
__global__ __launch_bounds__(256) void k_scores(const float* __restrict__ patch,
                                                const float* __restrict__ query) {
    __shared__ float4 q_sh[H_ * 128];   // 16 KB
    const int tid = threadIdx.x;
    for (int i = tid; i < H_ * 128; i += 256)
        q_sh[i] = ((const float4*)query)[i];
    __syncthreads();

    const int warp = tid >> 5, lane = tid & 31;
    const int gw = blockIdx.x * 8 + warp;     // 0..6271
    const int b = gw / P_;
    const int p = gw - b * P_;
    const float4* row = (const float4*)(patch + ((size_t)b * P_ + p) * D_);

    float acc[H_];
#pragma unroll
    for (int h = 0; h < H_; h++) acc[h] = 0.f;
#pragma unroll
    for (int i = 0; i < 4; i++) {
        float4 x = row[lane + i * 32];
#pragma unroll
        for (int h = 0; h < H_; h++) {
            float4 q = q_sh[h * 128 + lane + i * 32];
            acc[h] += x.x * q.x + x.y * q.y + x.z * q.z + x.w * q.w;
        }
    }
#pragma unroll
    for (int h = 0; h < H_; h++) {
#pragma unroll
        for (int o = 16; o; o >>= 1)
            acc[h] += __shfl_xor_sync(0xffffffffu, acc[h], o);
    }
    if (lane == 0) {
        float* s = g_scores + ((size_t)b * P_ + p) * H_;
#pragma unroll
        for (int h = 0; h < H_; h++) s[h] = acc[h];
    }
}

// ---------------------------------------------------------------------------
// Kernel 2: softmax over P + weighted pooling.
// grid (B_, 4 d-tiles), block 512 = 128 d x 4 p-quarters (49 p each).
// Inner loop: 7 loads in flight (MLP=7) -> ~1750 exposed cycles.
// ---------------------------------------------------------------------------
__global__ __launch_bounds__(512) void k_pool(const float* __restrict__ patch,
                                              float* __restrict__ sem_out) {
    __shared__ float w_sh[P_ * H_];         // 1568
    __shared__ float mmax[H_], inv_s[H_];
    __shared__ float psum[3 * 128 * H_];    // partials from p-quarters 1..3

    const int b  = blockIdx.x;
    const int dt = blockIdx.y;
    const int tid = threadIdx.x;
    const int warp = tid >> 5, lane = tid & 31;

    const float* sc = g_scores + (size_t)b * P_ * H_;
    for (int i = tid; i < P_ * H_; i += 512) w_sh[i] = sc[i];
    __syncthreads();

    if (warp < H_) {          // 8 warps compute 8 heads' stats
        const int h = warp;
        float m = -1e30f;
        for (int p = lane; p < P_; p += 32) m = fmaxf(m, w_sh[p * H_ + h]);
#pragma unroll
        for (int o = 16; o; o >>= 1) m = fmaxf(m, __shfl_xor_sync(0xffffffffu, m, o));
        float s = 0.f;
        for (int p = lane; p < P_; p += 32) s += __expf(w_sh[p * H_ + h] - m);
#pragma unroll
        for (int o = 16; o; o >>= 1) s += __shfl_xor_sync(0xffffffffu, s, o);
        if (lane == 0) { mmax[h] = m; inv_s[h] = 1.f / s; }
    }
    __syncthreads();
    for (int i = tid; i < P_ * H_; i += 512) {
        int h = i & (H_ - 1);
        w_sh[i] = __expf(w_sh[i] - mmax[h]) * inv_s[h];
    }
    __syncthreads();

    const int d_local = tid & 127;
    const int pq      = tid >> 7;          // 0..3
    const int d       = dt * 128 + d_local;
    const int p0      = pq * 49;
    const float* pb = patch + ((size_t)b * P_ + p0) * D_ + d;

    float acc[H_];
#pragma unroll
    for (int h = 0; h < H_; h++) acc[h] = 0.f;
#pragma unroll
    for (int r = 0; r < 7; r++) {
        float x[7];
#pragma unroll
        for (int q = 0; q < 7; q++) x[q] = pb[(r * 7 + q) * D_];
#pragma unroll
        for (int q = 0; q < 7; q++) {
            const float* wr = w_sh + (p0 + r * 7 + q) * H_;
#pragma unroll
            for (int h = 0; h < H_; h++) acc[h] = fmaf(wr[h], x[q], acc[h]);
        }
    }
    if (pq > 0) {
#pragma unroll
        for (int h = 0; h < H_; h++)
            psum[((pq - 1) * 128 + d_local) * H_ + h] = acc[h];
    }
    __syncthreads();
    if (pq == 0) {
#pragma unroll
        for (int h = 0; h < H_; h++) {
            float v = acc[h]
                    + psum[(0 * 128 + d_local) * H_ + h]
                    + psum[(1 * 128 + d_local) * H_ + h]
                    + psum[(2 * 128 + d_local) * H_ + h];
            sem_out[((size_t)b * H_ + h) * D_ + d] = v;
        }
    }
}

// ---------------------------------------------------------------------------
// Kernel 3: projections. grid 144 = 9 (8 heads + dom) x 16 e-tiles of 32.
// Block 256 computes a 32e x 32b tile, k-chunks of 64, 16.6 KB smem.
// ---------------------------------------------------------------------------
#define PROJ_SMEM_FLOATS 4160   // T 32x64 (2048) + W 32x65 (2080) + pad
__global__ __launch_bounds__(256) void k_proj(const float* __restrict__ sem_tok,
                                              const float* __restrict__ semW,
                                              const float* __restrict__ semb,
                                              const float* __restrict__ gf,
                                              const float* __restrict__ domW,
                                              const float* __restrict__ domb) {
    extern __shared__ float sh[];
    const int tid = threadIdx.x;
    const int y  = blockIdx.x >> 4;        // 0..8 (8 = domain)
    const int e0 = (blockIdx.x & 15) * 32;
    const bool dom = (y == 8);

    float4* Tsh4 = (float4*)sh;            // 32 rows x 16 float4
    float*  Wsh  = sh + 2048;              // 32 rows x 65 (padded)

    const float* Tbase   = dom ? gf : (sem_tok + (size_t)y * D_);
    const size_t Tstride = dom ? (size_t)D_ : (size_t)H_ * D_;
    const float* Wbase   = dom ? (domW + (size_t)e0 * D_)
                               : (semW + ((size_t)y * D_ + e0) * D_);

    const int e_local = tid & 31;
    const int bq      = tid >> 5;          // 0..7
    float acc[4] = {0.f, 0.f, 0.f, 0.f};

    for (int kc = 0; kc < D_; kc += 64) {
        const int bi = tid >> 4, kq = tid & 15;
#pragma unroll
        for (int rep = 0; rep < 2; rep++) {
            const int r = bi + rep * 16;
            Tsh4[r * 16 + kq] = ((const float4*)(Tbase + r * Tstride + kc))[kq];
            float4 w = ((const float4*)(Wbase + (size_t)r * D_ + kc))[kq];
            float* wd = Wsh + r * 65 + kq * 4;
            wd[0] = w.x; wd[1] = w.y; wd[2] = w.z; wd[3] = w.w;
        }
        __syncthreads();
#pragma unroll 4
        for (int k4 = 0; k4 < 16; k4++) {
            const float* wk = Wsh + e_local * 65 + k4 * 4;
            const float w0 = wk[0], w1 = wk[1], w2 = wk[2], w3 = wk[3];
#pragma unroll
            for (int j = 0; j < 4; j++) {
                float4 tv = Tsh4[(bq + 8 * j) * 16 + k4];
                acc[j] = fmaf(tv.x, w0, acc[j]);
                acc[j] = fmaf(tv.y, w1, acc[j]);
                acc[j] = fmaf(tv.z, w2, acc[j]);
                acc[j] = fmaf(tv.w, w3, acc[j]);
            }
        }
        __syncthreads();
    }
    const int e = e0 + e_local;
#pragma unroll
    for (int j = 0; j < 4; j++) {
        const int b = bq + 8 * j;
        if (dom) g_dom[b * D_ + e] = acc[j] + domb[e];
        else     g_sem[((size_t)b * H_ + y) * D_ + e] = acc[j] + semb[y * D_ + e];
    }
}

// ---------------------------------------------------------------------------
// Kernel S (side stream): data-independent tokens — prefix(0) + suffix(10)
// of every known unit. 65 MB of streaming stores, overlapped with compute.
// ---------------------------------------------------------------------------
__global__ __launch_bounds__(256) void k_static(const float4* __restrict__ pre,
                                                const float4* __restrict__ suf,
                                                float4* __restrict__ out) {
    const int u = blockIdx.x;
    const int c = u % C_;
    const int half = threadIdx.x >> 7, j = threadIdx.x & 127;
    const float4 v = half ? suf[(size_t)c * 128 + j] : pre[(size_t)c * 128 + j];
    __stcs(&out[(size_t)u * (11 * 128) + half * (10 * 128) + j], v);
}

// ---------------------------------------------------------------------------
// Kernel 4: dependent tokens (1..9) of known units + full unknown prompts.
// 295 MB streaming stores at max occupancy.
// ---------------------------------------------------------------------------
__global__ __launch_bounds__(256) void k_dep(const float4* __restrict__ upre,
                                             const float4* __restrict__ usem,
                                             const float4* __restrict__ usuf,
                                             float4* __restrict__ out,
                                             float4* __restrict__ unk_out) {
    const int u = blockIdx.x;
    if (u < NUNITS) {
        const int b = u / C_;
        float4* o = out + (size_t)u * (11 * 128) + 128;   // tokens 1..9
        const float4* dm = ((const float4*)g_dom) + b * 128;
        const float4* sm = ((const float4*)g_sem) + (size_t)b * H_ * 128;
        for (int i = threadIdx.x; i < 9 * 128; i += 256) {
            const int tk = i >> 7, j = i & 127;
            const float4 v = (tk == 0) ? dm[j] : sm[(tk - 1) * 128 + j];
            __stcs(&o[i], v);
        }
    } else {
        const int b = u - NUNITS;
        float4* o = unk_out + (size_t)b * 7 * 128;
        const float4* dm = ((const float4*)g_dom) + b * 128;
        for (int i = threadIdx.x; i < 7 * 128; i += 256) {
            const int tk = i >> 7, j = i & 127;
            float4 v;
            if (tk == 0)      v = upre[j];
            else if (tk == 1) v = dm[j];
            else if (tk < 6)  v = usem[(tk - 2) * 128 + j];
            else              v = usuf[j];
            __stcs(&o[i], v);
        }
    }
}

// ---------------------------------------------------------------------------
extern "C" void kernel_launch(void* const* d_in, const int* in_sizes, int n_in,
                              void* d_out, int out_size) {
    const float* patch = (const float*)d_in[0];
    const float* gf    = (const float*)d_in[1];
    const float* query = (const float*)d_in[2];
    const float* domW  = (const float*)d_in[3];
    const float* domb  = (const float*)d_in[4];
    const float* semW  = (const float*)d_in[5];
    const float* semb  = (const float*)d_in[6];
    const float* usem  = (const float*)d_in[7];
    const float* pre   = (const float*)d_in[8];
    const float* suf   = (const float*)d_in[9];
    const float* upre  = (const float*)d_in[10];
    const float* usuf  = (const float*)d_in[11];

    float* out     = (float*)d_out;
    float* unk_out = out + (size_t)KNOWN_ELEMS;
    float* sem_out = out + (size_t)KNOWN_ELEMS + UNK_ELEMS;

    // One-time side-stream/event setup (host objects; created on the first
    // call which is the non-captured correctness run). The SAME ops are
    // enqueued on every call — work is identical each invocation.
    static cudaStream_t s_side = nullptr;
    static cudaEvent_t evA = nullptr, evB = nullptr;
    if (s_side == nullptr) {
        cudaStreamCreateWithFlags(&s_side, cudaStreamNonBlocking);
        cudaEventCreateWithFlags(&evA, cudaEventDisableTiming);
        cudaEventCreateWithFlags(&evB, cudaEventDisableTiming);
    }

    // Fork: static writer runs on the side stream, concurrent with compute.
    cudaEventRecord(evA, 0);
    cudaStreamWaitEvent(s_side, evA, 0);
    k_static<<<NUNITS, 256, 0, s_side>>>((const float4*)pre, (const float4*)suf,
                                         (float4*)out);
    cudaEventRecord(evB, s_side);

    // Compute chain on the main (capture) stream.
    k_scores<<<(B_ * P_) / 8, 256>>>(patch, query);
    k_pool<<<dim3(B_, 4), 512>>>(patch, sem_out);
    k_proj<<<9 * 16, 256, PROJ_SMEM_FLOATS * 4>>>(sem_out, semW, semb,
                                                  gf, domW, domb);

    // Join, then the big dependent writer at full occupancy.
    cudaStreamWaitEvent(0, evB, 0);
    k_dep<<<NUNITS + B_, 256>>>((const float4*)upre, (const float4*)usem,
                                (const float4*)usuf,
                                (float4*)out, (float4*)unk_out);
}